// round 1
// baseline (speedup 1.0000x reference)
#include <cuda_runtime.h>
#include <cuda_bf16.h>
#include <cstdint>

// Problem constants
#define BATCH   16384
#define NA      32          // actions per row (== warp size, convenient)
#define KDIM    2048        // A*S_DIM
#define EDIM    128
#define NACT    1000
#define NOUT    64

#define FULLMASK 0xffffffffu

// ---------------------------------------------------------------------------
// Device scratch (no allocations allowed in kernel_launch)
// ---------------------------------------------------------------------------
__device__ __align__(16) __nv_bfloat16 g_Bhi[KDIM * NOUT];   // W_comb hi, chunked n-major
__device__ __align__(16) __nv_bfloat16 g_Blo[KDIM * NOUT];   // W_comb lo
__device__ __align__(16) float g_score[1024];                // per-action attention score
__device__ __align__(16) float g_proj[NACT * NOUT];          // table @ W_out2
__device__ __align__(16) float g_cbias[NOUT];                // b_state@W_out1 + b_out
__device__ __align__(16) float g_part[BATCH * NOUT];         // state @ W_comb

// ---------------------------------------------------------------------------
// K0a: W_comb = W_state[2048,128] @ W_out1[128,64], split to bf16 hi/lo,
//      stored chunked n-major: off = (kc*64 + j)*32 + kk, k = kc*32+kk.
// grid 64 blocks x 256 thr, each block handles 32 k-rows.
// ---------------------------------------------------------------------------
__global__ void k0a_wcomb(const float* __restrict__ W_state,
                          const float* __restrict__ W_out) {
    __shared__ float Wo[EDIM * NOUT];           // 32 KB
    const int tid = threadIdx.x;
    for (int i = tid; i < EDIM * NOUT; i += 256) Wo[i] = W_out[i];  // rows 0..127
    __syncthreads();

    const int rr = tid >> 4;          // 0..15
    const int jg = tid & 15;          // j = jg*4 .. +3
    const int k0 = blockIdx.x * 32;

    float acc0[4] = {0.f, 0.f, 0.f, 0.f};
    float acc1[4] = {0.f, 0.f, 0.f, 0.f};
    const float* w0 = W_state + (size_t)(k0 + rr) * EDIM;
    const float* w1 = W_state + (size_t)(k0 + rr + 16) * EDIM;

    #pragma unroll 4
    for (int e = 0; e < EDIM; ++e) {
        float4 o = *reinterpret_cast<const float4*>(Wo + e * NOUT + jg * 4);
        float x0 = __ldg(w0 + e);
        float x1 = __ldg(w1 + e);
        acc0[0] += x0 * o.x; acc0[1] += x0 * o.y; acc0[2] += x0 * o.z; acc0[3] += x0 * o.w;
        acc1[0] += x1 * o.x; acc1[1] += x1 * o.y; acc1[2] += x1 * o.z; acc1[3] += x1 * o.w;
    }

    const int kc = blockIdx.x;
    #pragma unroll
    for (int t = 0; t < 2; ++t) {
        const int kk = rr + t * 16;
        const float* acc = t ? acc1 : acc0;
        #pragma unroll
        for (int u = 0; u < 4; ++u) {
            const int j = jg * 4 + u;
            float v = acc[u];
            __nv_bfloat16 h = __float2bfloat16_rn(v);
            __nv_bfloat16 l = __float2bfloat16_rn(v - __bfloat162float(h));
            size_t off = ((size_t)kc * NOUT + j) * 32 + kk;
            g_Bhi[off] = h;
            g_Blo[off] = l;
        }
    }
}

// ---------------------------------------------------------------------------
// K0b: proj[a,:] = table[a] @ W_out2 ; score[a] = table[a]@W_att + b_att
// grid 32 blocks (32 table rows each) x 256 thr.
// ---------------------------------------------------------------------------
__global__ void k0b_tables(const float* __restrict__ table,
                           const float* __restrict__ W_att,
                           const float* __restrict__ b_att,
                           const float* __restrict__ W_out) {
    __shared__ float Wo[EDIM * NOUT];           // 32 KB (W_out2 = rows 128..255)
    const int tid = threadIdx.x;
    for (int i = tid; i < EDIM * NOUT; i += 256) Wo[i] = W_out[EDIM * NOUT + i];
    __syncthreads();

    const int rr = tid >> 4;
    const int jg = tid & 15;
    const int r0 = blockIdx.x * 32 + rr;
    const int r1 = r0 + 16;
    const bool v0 = r0 < NACT, v1 = r1 < NACT;

    float acc0[4] = {0.f, 0.f, 0.f, 0.f};
    float acc1[4] = {0.f, 0.f, 0.f, 0.f};

    #pragma unroll 4
    for (int e = 0; e < EDIM; ++e) {
        float4 o = *reinterpret_cast<const float4*>(Wo + e * NOUT + jg * 4);
        float x0 = v0 ? __ldg(table + (size_t)r0 * EDIM + e) : 0.f;
        float x1 = v1 ? __ldg(table + (size_t)r1 * EDIM + e) : 0.f;
        acc0[0] += x0 * o.x; acc0[1] += x0 * o.y; acc0[2] += x0 * o.z; acc0[3] += x0 * o.w;
        acc1[0] += x1 * o.x; acc1[1] += x1 * o.y; acc1[2] += x1 * o.z; acc1[3] += x1 * o.w;
    }
    if (v0) {
        #pragma unroll
        for (int u = 0; u < 4; ++u) g_proj[(size_t)r0 * NOUT + jg * 4 + u] = acc0[u];
    }
    if (v1) {
        #pragma unroll
        for (int u = 0; u < 4; ++u) g_proj[(size_t)r1 * NOUT + jg * 4 + u] = acc1[u];
    }

    if (tid < 32) {
        const int r = blockIdx.x * 32 + tid;
        if (r < NACT) {
            float s = __ldg(b_att);
            #pragma unroll 4
            for (int e = 0; e < EDIM; ++e)
                s += __ldg(table + (size_t)r * EDIM + e) * __ldg(W_att + e);
            g_score[r] = s;
        }
    }
}

// ---------------------------------------------------------------------------
// K0c: cbias = b_state @ W_out1 + b_out   (64 threads)
// ---------------------------------------------------------------------------
__global__ void k0c_bias(const float* __restrict__ b_state,
                         const float* __restrict__ W_out,
                         const float* __restrict__ b_out) {
    const int j = threadIdx.x;
    float s = b_out[j];
    #pragma unroll 4
    for (int e = 0; e < EDIM; ++e) s += b_state[e] * W_out[e * NOUT + j];
    g_cbias[j] = s;
}

// ---------------------------------------------------------------------------
// K1: g_part = state[16384,2048] @ W_comb[2048,64]  via bf16 3-split mma.sync
//     Tile: BM=64, BN=64, BK=32; 256 threads (8 warps, 2x4 warp grid,
//     warp tile 32x16 -> 2x2 m16n8k16 C tiles). Double-buffered SMEM,
//     fp32 -> bf16 hi/lo split on the fly.
// ---------------------------------------------------------------------------
__device__ __forceinline__ void mma16816(float* c, const uint32_t* a, const uint32_t* b) {
    asm volatile(
        "mma.sync.aligned.m16n8k16.row.col.f32.bf16.bf16.f32 "
        "{%0,%1,%2,%3},{%4,%5,%6,%7},{%8,%9},{%0,%1,%2,%3};\n"
        : "+f"(c[0]), "+f"(c[1]), "+f"(c[2]), "+f"(c[3])
        : "r"(a[0]), "r"(a[1]), "r"(a[2]), "r"(a[3]), "r"(b[0]), "r"(b[1]));
}

#define ASTRIDE 40   // padded smem row stride (bf16 elems) -> conflict-free frag LDS

__global__ __launch_bounds__(256, 2) void k1_gemm(const float* __restrict__ state) {
    // [buf][hi=0/lo=1][64 rows * 40]
    __shared__ __align__(16) __nv_bfloat16 sA[2][2][64 * ASTRIDE];
    __shared__ __align__(16) __nv_bfloat16 sB[2][2][64 * ASTRIDE];

    const int tid  = threadIdx.x;
    const int lane = tid & 31;
    const int wid  = tid >> 5;
    const int wm   = wid & 1;        // 0..1  (32 rows each)
    const int wn   = wid >> 1;       // 0..3  (16 cols each)
    const int tg   = lane >> 2;      // 0..7
    const int tq   = lane & 3;       // 0..3
    const int blockRow = blockIdx.x * 64;

    // A prefetch mapping: thread covers (row ar0, q) and (row ar0+32, q), q in float4 units
    const int ar0 = tid >> 3;        // 0..31
    const int aq  = tid & 7;         // 0..7
    // B prefetch mapping: thread covers (n=bn, kk = bkb*8 .. +7)
    const int bn  = tid >> 2;        // 0..63
    const int bkb = tid & 3;         // 0..3

    const float* gA0 = state + (size_t)(blockRow + ar0) * KDIM + aq * 4;
    const float* gA1 = state + (size_t)(blockRow + ar0 + 32) * KDIM + aq * 4;
    const size_t gBoff = (size_t)bn * 32 + bkb * 8;

    float4 apf0 = *reinterpret_cast<const float4*>(gA0);
    float4 apf1 = *reinterpret_cast<const float4*>(gA1);
    uint4  bhpf = *reinterpret_cast<const uint4*>(g_Bhi + gBoff);
    uint4  blpf = *reinterpret_cast<const uint4*>(g_Blo + gBoff);

    float C[2][2][4];
    #pragma unroll
    for (int mt = 0; mt < 2; ++mt)
        #pragma unroll
        for (int nt = 0; nt < 2; ++nt)
            #pragma unroll
            for (int u = 0; u < 4; ++u) C[mt][nt][u] = 0.f;

    const int aoff0 = ar0 * ASTRIDE + aq * 4;
    const int aoff1 = (ar0 + 32) * ASTRIDE + aq * 4;
    const int boff  = bn * ASTRIDE + bkb * 8;

    for (int it = 0; it < KDIM / 32; ++it) {
        const int buf = it & 1;

        // --- split + STS A (two float4 -> hi/lo bf16x4 each) ---
        {
            float4 f = apf0;
            __nv_bfloat16 h0 = __float2bfloat16_rn(f.x), h1 = __float2bfloat16_rn(f.y);
            __nv_bfloat16 h2 = __float2bfloat16_rn(f.z), h3 = __float2bfloat16_rn(f.w);
            __nv_bfloat16 l0 = __float2bfloat16_rn(f.x - __bfloat162float(h0));
            __nv_bfloat16 l1 = __float2bfloat16_rn(f.y - __bfloat162float(h1));
            __nv_bfloat16 l2 = __float2bfloat16_rn(f.z - __bfloat162float(h2));
            __nv_bfloat16 l3 = __float2bfloat16_rn(f.w - __bfloat162float(h3));
            __nv_bfloat162 ph0 = __halves2bfloat162(h0, h1), ph1 = __halves2bfloat162(h2, h3);
            __nv_bfloat162 pl0 = __halves2bfloat162(l0, l1), pl1 = __halves2bfloat162(l2, l3);
            *reinterpret_cast<uint2*>(&sA[buf][0][aoff0]) =
                make_uint2(*reinterpret_cast<uint32_t*>(&ph0), *reinterpret_cast<uint32_t*>(&ph1));
            *reinterpret_cast<uint2*>(&sA[buf][1][aoff0]) =
                make_uint2(*reinterpret_cast<uint32_t*>(&pl0), *reinterpret_cast<uint32_t*>(&pl1));
        }
        {
            float4 f = apf1;
            __nv_bfloat16 h0 = __float2bfloat16_rn(f.x), h1 = __float2bfloat16_rn(f.y);
            __nv_bfloat16 h2 = __float2bfloat16_rn(f.z), h3 = __float2bfloat16_rn(f.w);
            __nv_bfloat16 l0 = __float2bfloat16_rn(f.x - __bfloat162float(h0));
            __nv_bfloat16 l1 = __float2bfloat16_rn(f.y - __bfloat162float(h1));
            __nv_bfloat16 l2 = __float2bfloat16_rn(f.z - __bfloat162float(h2));
            __nv_bfloat16 l3 = __float2bfloat16_rn(f.w - __bfloat162float(h3));
            __nv_bfloat162 ph0 = __halves2bfloat162(h0, h1), ph1 = __halves2bfloat162(h2, h3);
            __nv_bfloat162 pl0 = __halves2bfloat162(l0, l1), pl1 = __halves2bfloat162(l2, l3);
            *reinterpret_cast<uint2*>(&sA[buf][0][aoff1]) =
                make_uint2(*reinterpret_cast<uint32_t*>(&ph0), *reinterpret_cast<uint32_t*>(&ph1));
            *reinterpret_cast<uint2*>(&sA[buf][1][aoff1]) =
                make_uint2(*reinterpret_cast<uint32_t*>(&pl0), *reinterpret_cast<uint32_t*>(&pl1));
        }
        // --- STS B hi/lo ---
        *reinterpret_cast<uint2*>(&sB[buf][0][boff])     = make_uint2(bhpf.x, bhpf.y);
        *reinterpret_cast<uint2*>(&sB[buf][0][boff + 4]) = make_uint2(bhpf.z, bhpf.w);
        *reinterpret_cast<uint2*>(&sB[buf][1][boff])     = make_uint2(blpf.x, blpf.y);
        *reinterpret_cast<uint2*>(&sB[buf][1][boff + 4]) = make_uint2(blpf.z, blpf.w);

        __syncthreads();

        // --- prefetch next tile ---
        if (it < KDIM / 32 - 1) {
            const int k0 = (it + 1) * 32;
            apf0 = *reinterpret_cast<const float4*>(gA0 + k0);
            apf1 = *reinterpret_cast<const float4*>(gA1 + k0);
            bhpf = *reinterpret_cast<const uint4*>(g_Bhi + (size_t)(it + 1) * 2048 + gBoff);
            blpf = *reinterpret_cast<const uint4*>(g_Blo + (size_t)(it + 1) * 2048 + gBoff);
        }

        // --- compute: 2 k-steps of 16 ---
        #pragma unroll
        for (int ks = 0; ks < 2; ++ks) {
            const int kb = ks * 16;
            uint32_t ah[2][4], al[2][4], bh[2][2], bl[2][2];
            #pragma unroll
            for (int mt = 0; mt < 2; ++mt) {
                const int base = (wm * 32 + mt * 16 + tg) * ASTRIDE + kb + tq * 2;
                ah[mt][0] = *reinterpret_cast<const uint32_t*>(&sA[buf][0][base]);
                ah[mt][1] = *reinterpret_cast<const uint32_t*>(&sA[buf][0][base + 8 * ASTRIDE]);
                ah[mt][2] = *reinterpret_cast<const uint32_t*>(&sA[buf][0][base + 8]);
                ah[mt][3] = *reinterpret_cast<const uint32_t*>(&sA[buf][0][base + 8 * ASTRIDE + 8]);
                al[mt][0] = *reinterpret_cast<const uint32_t*>(&sA[buf][1][base]);
                al[mt][1] = *reinterpret_cast<const uint32_t*>(&sA[buf][1][base + 8 * ASTRIDE]);
                al[mt][2] = *reinterpret_cast<const uint32_t*>(&sA[buf][1][base + 8]);
                al[mt][3] = *reinterpret_cast<const uint32_t*>(&sA[buf][1][base + 8 * ASTRIDE + 8]);
            }
            #pragma unroll
            for (int nt = 0; nt < 2; ++nt) {
                const int baseB = (wn * 16 + nt * 8 + tg) * ASTRIDE + kb + tq * 2;
                bh[nt][0] = *reinterpret_cast<const uint32_t*>(&sB[buf][0][baseB]);
                bh[nt][1] = *reinterpret_cast<const uint32_t*>(&sB[buf][0][baseB + 8]);
                bl[nt][0] = *reinterpret_cast<const uint32_t*>(&sB[buf][1][baseB]);
                bl[nt][1] = *reinterpret_cast<const uint32_t*>(&sB[buf][1][baseB + 8]);
            }
            #pragma unroll
            for (int mt = 0; mt < 2; ++mt)
                #pragma unroll
                for (int nt = 0; nt < 2; ++nt) {
                    mma16816(C[mt][nt], ah[mt], bh[nt]);   // hi*hi
                    mma16816(C[mt][nt], ah[mt], bl[nt]);   // hi*lo
                    mma16816(C[mt][nt], al[mt], bh[nt]);   // lo*hi
                }
        }
    }

    // epilogue: write C to g_part
    #pragma unroll
    for (int mt = 0; mt < 2; ++mt)
        #pragma unroll
        for (int nt = 0; nt < 2; ++nt) {
            const int r0 = blockRow + wm * 32 + mt * 16 + tg;
            const int cc = wn * 16 + nt * 8 + tq * 2;
            float2 v0 = make_float2(C[mt][nt][0], C[mt][nt][1]);
            float2 v1 = make_float2(C[mt][nt][2], C[mt][nt][3]);
            *reinterpret_cast<float2*>(g_part + (size_t)r0 * NOUT + cc) = v0;
            *reinterpret_cast<float2*>(g_part + (size_t)(r0 + 8) * NOUT + cc) = v1;
        }
}

// ---------------------------------------------------------------------------
// K2: per-row softmax over precomputed scores + weighted gather of proj rows.
//     One warp per batch row (A == 32 == warp size). 8 rows per block.
// ---------------------------------------------------------------------------
__global__ __launch_bounds__(256) void k2_attend(const int* __restrict__ action,
                                                 float* __restrict__ out) {
    const int wid  = threadIdx.x >> 5;
    const int lane = threadIdx.x & 31;
    const int b = blockIdx.x * 8 + wid;

    const int idx = action[(size_t)b * NA + lane];
    float s = g_score[idx];

    float m = s;
    #pragma unroll
    for (int o = 16; o > 0; o >>= 1) m = fmaxf(m, __shfl_xor_sync(FULLMASK, m, o));
    float e = __expf(s - m);
    float sum = e;
    #pragma unroll
    for (int o = 16; o > 0; o >>= 1) sum += __shfl_xor_sync(FULLMASK, sum, o);
    const float w = e / sum;

    float2 acc = *reinterpret_cast<const float2*>(g_part + (size_t)b * NOUT + lane * 2);
    float2 cb  = *reinterpret_cast<const float2*>(g_cbias + lane * 2);
    acc.x += cb.x; acc.y += cb.y;

    #pragma unroll
    for (int a = 0; a < NA; ++a) {
        const float wa = __shfl_sync(FULLMASK, w, a);
        const int   ia = __shfl_sync(FULLMASK, idx, a);
        float2 p = *reinterpret_cast<const float2*>(g_proj + (size_t)ia * NOUT + lane * 2);
        acc.x = fmaf(wa, p.x, acc.x);
        acc.y = fmaf(wa, p.y, acc.y);
    }
    *reinterpret_cast<float2*>(out + (size_t)b * NOUT + lane * 2) = acc;
}

// ---------------------------------------------------------------------------
// kernel_launch
// ---------------------------------------------------------------------------
extern "C" void kernel_launch(void* const* d_in, const int* in_sizes, int n_in,
                              void* d_out, int out_size) {
    const float* state   = (const float*)d_in[0];
    const int*   action  = (const int*)  d_in[1];
    const float* W_state = (const float*)d_in[2];
    const float* b_state = (const float*)d_in[3];
    const float* table   = (const float*)d_in[4];
    const float* W_att   = (const float*)d_in[5];
    const float* b_att   = (const float*)d_in[6];
    const float* W_out   = (const float*)d_in[7];
    const float* b_out   = (const float*)d_in[8];
    float* out = (float*)d_out;

    k0a_wcomb <<<KDIM / 32, 256>>>(W_state, W_out);
    k0b_tables<<<(NACT + 31) / 32, 256>>>(table, W_att, b_att, W_out);
    k0c_bias  <<<1, NOUT>>>(b_state, W_out, b_out);
    k1_gemm   <<<BATCH / 64, 256>>>(state);
    k2_attend <<<BATCH / 8, 256>>>(action, out);
}

// round 2
// speedup vs baseline: 1.0164x; 1.0164x over previous
#include <cuda_runtime.h>
#include <cuda_bf16.h>
#include <cstdint>

#define BATCH   16384
#define NA      32
#define KDIM    2048
#define EDIM    128
#define NACT    1000
#define NOUT    64
#define NIT     (KDIM / 32)

#define FULLMASK 0xffffffffu

// ---------------------------------------------------------------------------
// Device scratch
// ---------------------------------------------------------------------------
__device__ __align__(16) __nv_bfloat16 g_Bhi[KDIM * NOUT];   // W_comb hi, chunked n-major
__device__ __align__(16) __nv_bfloat16 g_Blo[KDIM * NOUT];   // W_comb lo
__device__ __align__(16) float g_score[1024];                // per-action attention score
__device__ __align__(16) float g_proj[NACT * NOUT];          // table @ W_out2
__device__ __align__(16) float g_cbias[NOUT];                // b_state@W_out1 + b_out

// ---------------------------------------------------------------------------
// K0a: W_comb = W_state[2048,128] @ W_out1[128,64] -> bf16 hi/lo, chunked n-major
// ---------------------------------------------------------------------------
__global__ void k0a_wcomb(const float* __restrict__ W_state,
                          const float* __restrict__ W_out) {
    __shared__ float Wo[EDIM * NOUT];
    const int tid = threadIdx.x;
    for (int i = tid; i < EDIM * NOUT; i += 256) Wo[i] = W_out[i];
    __syncthreads();

    const int rr = tid >> 4;
    const int jg = tid & 15;
    const int k0 = blockIdx.x * 32;

    float acc0[4] = {0.f, 0.f, 0.f, 0.f};
    float acc1[4] = {0.f, 0.f, 0.f, 0.f};
    const float* w0 = W_state + (size_t)(k0 + rr) * EDIM;
    const float* w1 = W_state + (size_t)(k0 + rr + 16) * EDIM;

    #pragma unroll 4
    for (int e = 0; e < EDIM; ++e) {
        float4 o = *reinterpret_cast<const float4*>(Wo + e * NOUT + jg * 4);
        float x0 = __ldg(w0 + e);
        float x1 = __ldg(w1 + e);
        acc0[0] += x0 * o.x; acc0[1] += x0 * o.y; acc0[2] += x0 * o.z; acc0[3] += x0 * o.w;
        acc1[0] += x1 * o.x; acc1[1] += x1 * o.y; acc1[2] += x1 * o.z; acc1[3] += x1 * o.w;
    }

    const int kc = blockIdx.x;
    #pragma unroll
    for (int t = 0; t < 2; ++t) {
        const int kk = rr + t * 16;
        const float* acc = t ? acc1 : acc0;
        #pragma unroll
        for (int u = 0; u < 4; ++u) {
            const int j = jg * 4 + u;
            float v = acc[u];
            __nv_bfloat16 h = __float2bfloat16_rn(v);
            __nv_bfloat16 l = __float2bfloat16_rn(v - __bfloat162float(h));
            size_t off = ((size_t)kc * NOUT + j) * 32 + kk;
            g_Bhi[off] = h;
            g_Blo[off] = l;
        }
    }
}

// ---------------------------------------------------------------------------
// K0b: proj = table @ W_out2 ; score = table@W_att + b_att
// ---------------------------------------------------------------------------
__global__ void k0b_tables(const float* __restrict__ table,
                           const float* __restrict__ W_att,
                           const float* __restrict__ b_att,
                           const float* __restrict__ W_out) {
    __shared__ float Wo[EDIM * NOUT];
    const int tid = threadIdx.x;
    for (int i = tid; i < EDIM * NOUT; i += 256) Wo[i] = W_out[EDIM * NOUT + i];
    __syncthreads();

    const int rr = tid >> 4;
    const int jg = tid & 15;
    const int r0 = blockIdx.x * 32 + rr;
    const int r1 = r0 + 16;
    const bool v0 = r0 < NACT, v1 = r1 < NACT;

    float acc0[4] = {0.f, 0.f, 0.f, 0.f};
    float acc1[4] = {0.f, 0.f, 0.f, 0.f};

    #pragma unroll 4
    for (int e = 0; e < EDIM; ++e) {
        float4 o = *reinterpret_cast<const float4*>(Wo + e * NOUT + jg * 4);
        float x0 = v0 ? __ldg(table + (size_t)r0 * EDIM + e) : 0.f;
        float x1 = v1 ? __ldg(table + (size_t)r1 * EDIM + e) : 0.f;
        acc0[0] += x0 * o.x; acc0[1] += x0 * o.y; acc0[2] += x0 * o.z; acc0[3] += x0 * o.w;
        acc1[0] += x1 * o.x; acc1[1] += x1 * o.y; acc1[2] += x1 * o.z; acc1[3] += x1 * o.w;
    }
    if (v0) {
        #pragma unroll
        for (int u = 0; u < 4; ++u) g_proj[(size_t)r0 * NOUT + jg * 4 + u] = acc0[u];
    }
    if (v1) {
        #pragma unroll
        for (int u = 0; u < 4; ++u) g_proj[(size_t)r1 * NOUT + jg * 4 + u] = acc1[u];
    }

    if (tid < 32) {
        const int r = blockIdx.x * 32 + tid;
        if (r < NACT) {
            float s = __ldg(b_att);
            #pragma unroll 4
            for (int e = 0; e < EDIM; ++e)
                s += __ldg(table + (size_t)r * EDIM + e) * __ldg(W_att + e);
            g_score[r] = s;
        }
    }
}

// ---------------------------------------------------------------------------
// K0c: cbias = b_state @ W_out1 + b_out
// ---------------------------------------------------------------------------
__global__ void k0c_bias(const float* __restrict__ b_state,
                         const float* __restrict__ W_out,
                         const float* __restrict__ b_out) {
    const int j = threadIdx.x;
    float s = b_out[j];
    #pragma unroll 4
    for (int e = 0; e < EDIM; ++e) s += b_state[e] * W_out[e * NOUT + j];
    g_cbias[j] = s;
}

// ---------------------------------------------------------------------------
// K1: state @ W_comb via bf16 3-split mma.sync, prefetch-depth-2,
//     ldmatrix fragment loads, fused softmax-attention epilogue.
// ---------------------------------------------------------------------------
__device__ __forceinline__ void mma16816(float* c, const uint32_t* a, const uint32_t* b) {
    asm volatile(
        "mma.sync.aligned.m16n8k16.row.col.f32.bf16.bf16.f32 "
        "{%0,%1,%2,%3},{%4,%5,%6,%7},{%8,%9},{%0,%1,%2,%3};\n"
        : "+f"(c[0]), "+f"(c[1]), "+f"(c[2]), "+f"(c[3])
        : "r"(a[0]), "r"(a[1]), "r"(a[2]), "r"(a[3]), "r"(b[0]), "r"(b[1]));
}

__device__ __forceinline__ void ldsm_x4(uint32_t* r, uint32_t addr) {
    asm volatile("ldmatrix.sync.aligned.m8n8.x4.shared.b16 {%0,%1,%2,%3}, [%4];"
                 : "=r"(r[0]), "=r"(r[1]), "=r"(r[2]), "=r"(r[3]) : "r"(addr));
}
__device__ __forceinline__ void ldsm_x2(uint32_t* r, uint32_t addr) {
    asm volatile("ldmatrix.sync.aligned.m8n8.x2.shared.b16 {%0,%1}, [%2];"
                 : "=r"(r[0]), "=r"(r[1]) : "r"(addr));
}

#define ASTRIDE 40          // padded smem row stride (bf16 elems)
#define CSTRIDE 72          // padded fp32 stride for epilogue C tile

__global__ __launch_bounds__(256, 2) void k1_gemm(const float* __restrict__ state,
                                                  const int* __restrict__ action,
                                                  float* __restrict__ out) {
    __shared__ __align__(16) __nv_bfloat16 sA[2][2][64 * ASTRIDE];  // [buf][hi/lo]
    __shared__ __align__(16) __nv_bfloat16 sB[2][2][64 * ASTRIDE];

    const int tid  = threadIdx.x;
    const int lane = tid & 31;
    const int wid  = tid >> 5;
    const int wm   = wid & 1;
    const int wn   = wid >> 1;
    const int tg   = lane >> 2;
    const int tq   = lane & 3;
    const int blockRow = blockIdx.x * 64;

    const int ar0 = tid >> 3;
    const int aq  = tid & 7;
    const int bn  = tid >> 2;
    const int bkb = tid & 3;

    const float* gA0 = state + (size_t)(blockRow + ar0) * KDIM + aq * 4;
    const float* gA1 = state + (size_t)(blockRow + ar0 + 32) * KDIM + aq * 4;
    const size_t gBoff = (size_t)bn * 32 + bkb * 8;

    // prefetch regs: 2 slots (depth 2)
    float4 a0p0 = *reinterpret_cast<const float4*>(gA0);
    float4 a1p0 = *reinterpret_cast<const float4*>(gA1);
    uint4  bhp0 = *reinterpret_cast<const uint4*>(g_Bhi + gBoff);
    uint4  blp0 = *reinterpret_cast<const uint4*>(g_Blo + gBoff);
    float4 a0p1 = *reinterpret_cast<const float4*>(gA0 + 32);
    float4 a1p1 = *reinterpret_cast<const float4*>(gA1 + 32);
    uint4  bhp1 = *reinterpret_cast<const uint4*>(g_Bhi + 2048 + gBoff);
    uint4  blp1 = *reinterpret_cast<const uint4*>(g_Blo + 2048 + gBoff);

    float C[2][2][4];
    #pragma unroll
    for (int mt = 0; mt < 2; ++mt)
        #pragma unroll
        for (int nt = 0; nt < 2; ++nt)
            #pragma unroll
            for (int u = 0; u < 4; ++u) C[mt][nt][u] = 0.f;

    const int aoff0 = ar0 * ASTRIDE + aq * 4;
    const int aoff1 = (ar0 + 32) * ASTRIDE + aq * 4;
    const int boff  = bn * ASTRIDE + bkb * 8;

    // ldmatrix lane-base addresses (bytes into shared space)
    const uint32_t aLaneOff = (uint32_t)(((wm * 32 + (lane & 15)) * ASTRIDE + (lane >> 4) * 8) * 2);
    const uint32_t bLaneOff = (uint32_t)(((wn * 16 + (lane & 7)) * ASTRIDE + ((lane >> 3) & 1) * 8) * 2);
    uint32_t aBase00 = (uint32_t)__cvta_generic_to_shared(&sA[0][0][0]) + aLaneOff;
    uint32_t aBase01 = (uint32_t)__cvta_generic_to_shared(&sA[0][1][0]) + aLaneOff;
    uint32_t aBase10 = (uint32_t)__cvta_generic_to_shared(&sA[1][0][0]) + aLaneOff;
    uint32_t aBase11 = (uint32_t)__cvta_generic_to_shared(&sA[1][1][0]) + aLaneOff;
    uint32_t bBase00 = (uint32_t)__cvta_generic_to_shared(&sB[0][0][0]) + bLaneOff;
    uint32_t bBase01 = (uint32_t)__cvta_generic_to_shared(&sB[0][1][0]) + bLaneOff;
    uint32_t bBase10 = (uint32_t)__cvta_generic_to_shared(&sB[1][0][0]) + bLaneOff;
    uint32_t bBase11 = (uint32_t)__cvta_generic_to_shared(&sB[1][1][0]) + bLaneOff;

#define SPLIT_STS(F, BUF, OFF)                                                        \
    {                                                                                 \
        float4 f = (F);                                                               \
        __nv_bfloat16 h0 = __float2bfloat16_rn(f.x), h1 = __float2bfloat16_rn(f.y);   \
        __nv_bfloat16 h2 = __float2bfloat16_rn(f.z), h3 = __float2bfloat16_rn(f.w);   \
        __nv_bfloat16 l0 = __float2bfloat16_rn(f.x - __bfloat162float(h0));           \
        __nv_bfloat16 l1 = __float2bfloat16_rn(f.y - __bfloat162float(h1));           \
        __nv_bfloat16 l2 = __float2bfloat16_rn(f.z - __bfloat162float(h2));           \
        __nv_bfloat16 l3 = __float2bfloat16_rn(f.w - __bfloat162float(h3));           \
        __nv_bfloat162 ph0 = __halves2bfloat162(h0, h1), ph1 = __halves2bfloat162(h2, h3); \
        __nv_bfloat162 pl0 = __halves2bfloat162(l0, l1), pl1 = __halves2bfloat162(l2, l3); \
        *reinterpret_cast<uint2*>(&sA[BUF][0][OFF]) =                                 \
            make_uint2(*reinterpret_cast<uint32_t*>(&ph0), *reinterpret_cast<uint32_t*>(&ph1)); \
        *reinterpret_cast<uint2*>(&sA[BUF][1][OFF]) =                                 \
            make_uint2(*reinterpret_cast<uint32_t*>(&pl0), *reinterpret_cast<uint32_t*>(&pl1)); \
    }

#define COMPUTE(AH_BASE, AL_BASE, BH_BASE, BL_BASE)                                   \
    {                                                                                 \
        _Pragma("unroll")                                                             \
        for (int ks = 0; ks < 2; ++ks) {                                              \
            const uint32_t kbB = (uint32_t)(ks * 16 * 2);                             \
            uint32_t ah[2][4], al[2][4], bh[2][2], bl[2][2];                          \
            _Pragma("unroll")                                                         \
            for (int mt = 0; mt < 2; ++mt) {                                          \
                const uint32_t moff = (uint32_t)(mt * 16 * ASTRIDE * 2) + kbB;        \
                ldsm_x4(ah[mt], (AH_BASE) + moff);                                    \
                ldsm_x4(al[mt], (AL_BASE) + moff);                                    \
            }                                                                         \
            _Pragma("unroll")                                                         \
            for (int nt = 0; nt < 2; ++nt) {                                          \
                const uint32_t noff = (uint32_t)(nt * 8 * ASTRIDE * 2) + kbB;         \
                ldsm_x2(bh[nt], (BH_BASE) + noff);                                    \
                ldsm_x2(bl[nt], (BL_BASE) + noff);                                    \
            }                                                                         \
            _Pragma("unroll")                                                         \
            for (int mt = 0; mt < 2; ++mt)                                            \
                _Pragma("unroll")                                                     \
                for (int nt = 0; nt < 2; ++nt) {                                      \
                    mma16816(C[mt][nt], ah[mt], bh[nt]);                              \
                    mma16816(C[mt][nt], ah[mt], bl[nt]);                              \
                    mma16816(C[mt][nt], al[mt], bh[nt]);                              \
                }                                                                     \
        }                                                                             \
    }

    #pragma unroll 1
    for (int it = 0; it < NIT; it += 2) {
        // ---- even: buf 0, consume slot 0, reload slot 0 for it+2 ----
        SPLIT_STS(a0p0, 0, aoff0);
        SPLIT_STS(a1p0, 0, aoff1);
        *reinterpret_cast<uint2*>(&sB[0][0][boff])     = make_uint2(bhp0.x, bhp0.y);
        *reinterpret_cast<uint2*>(&sB[0][0][boff + 4]) = make_uint2(bhp0.z, bhp0.w);
        *reinterpret_cast<uint2*>(&sB[0][1][boff])     = make_uint2(blp0.x, blp0.y);
        *reinterpret_cast<uint2*>(&sB[0][1][boff + 4]) = make_uint2(blp0.z, blp0.w);
        __syncthreads();
        if (it + 2 < NIT) {
            const int k0 = (it + 2) * 32;
            a0p0 = *reinterpret_cast<const float4*>(gA0 + k0);
            a1p0 = *reinterpret_cast<const float4*>(gA1 + k0);
            bhp0 = *reinterpret_cast<const uint4*>(g_Bhi + (size_t)(it + 2) * 2048 + gBoff);
            blp0 = *reinterpret_cast<const uint4*>(g_Blo + (size_t)(it + 2) * 2048 + gBoff);
        }
        COMPUTE(aBase00, aBase01, bBase00, bBase01);

        // ---- odd: buf 1, consume slot 1, reload slot 1 for it+3 ----
        SPLIT_STS(a0p1, 1, aoff0);
        SPLIT_STS(a1p1, 1, aoff1);
        *reinterpret_cast<uint2*>(&sB[1][0][boff])     = make_uint2(bhp1.x, bhp1.y);
        *reinterpret_cast<uint2*>(&sB[1][0][boff + 4]) = make_uint2(bhp1.z, bhp1.w);
        *reinterpret_cast<uint2*>(&sB[1][1][boff])     = make_uint2(blp1.x, blp1.y);
        *reinterpret_cast<uint2*>(&sB[1][1][boff + 4]) = make_uint2(blp1.z, blp1.w);
        __syncthreads();
        if (it + 3 < NIT) {
            const int k0 = (it + 3) * 32;
            a0p1 = *reinterpret_cast<const float4*>(gA0 + k0);
            a1p1 = *reinterpret_cast<const float4*>(gA1 + k0);
            bhp1 = *reinterpret_cast<const uint4*>(g_Bhi + (size_t)(it + 3) * 2048 + gBoff);
            blp1 = *reinterpret_cast<const uint4*>(g_Blo + (size_t)(it + 3) * 2048 + gBoff);
        }
        COMPUTE(aBase10, aBase11, bBase10, bBase11);
    }

    // ================= fused epilogue =================
    __syncthreads();
    float* Cs = reinterpret_cast<float*>(&sA[0][0][0]);  // 64 x CSTRIDE fp32 (18.4KB <= 20.4KB)

    #pragma unroll
    for (int mt = 0; mt < 2; ++mt)
        #pragma unroll
        for (int nt = 0; nt < 2; ++nt) {
            const int r0 = wm * 32 + mt * 16 + tg;
            const int cc = wn * 16 + nt * 8 + tq * 2;
            *reinterpret_cast<float2*>(Cs + r0 * CSTRIDE + cc) =
                make_float2(C[mt][nt][0], C[mt][nt][1]);
            *reinterpret_cast<float2*>(Cs + (r0 + 8) * CSTRIDE + cc) =
                make_float2(C[mt][nt][2], C[mt][nt][3]);
        }
    __syncthreads();

    // each warp handles 8 batch rows: softmax over 32 action scores + proj gather
    const float2 cb = *reinterpret_cast<const float2*>(g_cbias + lane * 2);
    #pragma unroll 1
    for (int rr = 0; rr < 8; ++rr) {
        const int rloc = wid * 8 + rr;
        const int b = blockRow + rloc;
        const int idx = __ldg(action + (size_t)b * NA + lane);
        float s = g_score[idx];

        float m = s;
        #pragma unroll
        for (int o = 16; o > 0; o >>= 1) m = fmaxf(m, __shfl_xor_sync(FULLMASK, m, o));
        float e = __expf(s - m);
        float sum = e;
        #pragma unroll
        for (int o = 16; o > 0; o >>= 1) sum += __shfl_xor_sync(FULLMASK, sum, o);
        const float w = e / sum;

        float2 acc = *reinterpret_cast<const float2*>(Cs + rloc * CSTRIDE + lane * 2);
        acc.x += cb.x; acc.y += cb.y;

        #pragma unroll
        for (int a = 0; a < NA; ++a) {
            const float wa = __shfl_sync(FULLMASK, w, a);
            const int   ia = __shfl_sync(FULLMASK, idx, a);
            float2 p = *reinterpret_cast<const float2*>(g_proj + (size_t)ia * NOUT + lane * 2);
            acc.x = fmaf(wa, p.x, acc.x);
            acc.y = fmaf(wa, p.y, acc.y);
        }
        *reinterpret_cast<float2*>(out + (size_t)b * NOUT + lane * 2) = acc;
    }
}

// ---------------------------------------------------------------------------
// kernel_launch
// ---------------------------------------------------------------------------
extern "C" void kernel_launch(void* const* d_in, const int* in_sizes, int n_in,
                              void* d_out, int out_size) {
    const float* state   = (const float*)d_in[0];
    const int*   action  = (const int*)  d_in[1];
    const float* W_state = (const float*)d_in[2];
    const float* b_state = (const float*)d_in[3];
    const float* table   = (const float*)d_in[4];
    const float* W_att   = (const float*)d_in[5];
    const float* b_att   = (const float*)d_in[6];
    const float* W_out   = (const float*)d_in[7];
    const float* b_out   = (const float*)d_in[8];
    float* out = (float*)d_out;

    k0a_wcomb <<<KDIM / 32, 256>>>(W_state, W_out);
    k0b_tables<<<(NACT + 31) / 32, 256>>>(table, W_att, b_att, W_out);
    k0c_bias  <<<1, NOUT>>>(b_state, W_out, b_out);
    k1_gemm   <<<BATCH / 64, 256>>>(state, action, out);
}